// round 10
// baseline (speedup 1.0000x reference)
#include <cuda_runtime.h>
#include <math.h>

#define C        144
#define W        77
#define KW       10
#define FC       64
#define CONV_OUT 68                    // W - KW + 1
#define CONCAT   (C*FC + CONV_OUT)     // 9284 floats = 2321 float4 exactly
#define NV4      (CONCAT / 4)          // 2321
#define H2       128
#define K1GRID   (C + 1)               // 144 fc blocks + 1 conv block
#define K1NT     1024
#define K2GRID   H2
#define K2NT     512

// Scratch (no device allocation allowed); g_acc/g_cnt reset by K2's last block.
__device__ __align__(16) float g_concat[CONCAT];
__device__ float        g_acc = 0.0f;
__device__ unsigned int g_cnt = 0u;

__device__ __forceinline__ float warp_reduce(float v) {
#pragma unroll
    for (int o = 16; o > 0; o >>= 1) v += __shfl_down_sync(0xffffffffu, v, o);
    return v;
}

__device__ __forceinline__ float dot4(float4 a, float4 b) {
    return a.x * b.x + a.y * b.y + a.z * b.z + a.w * b.w;
}

// ---------------------------------------------------------------------------
// K1: produce g_concat. No global atomics, no fences, no barrier in fc blocks.
//   Blocks 0..143 : channel c -> 64 FC outputs (32 warps x 2, front-batched
//                   loads, warp reduce, lane0 STG). Zero __syncthreads.
//   Block 144     : conv (x in smem, warps over channels, smem atomics).
//   Triggers the dependent K2 launch immediately at entry (PDL).
// ---------------------------------------------------------------------------
__global__ __launch_bounds__(K1NT, 1) void k1_concat(
    const float* __restrict__ x,       // [C, W]
    const float* __restrict__ fc_w,    // [C, FC, W]
    const float* __restrict__ fc_b,    // [C, FC]
    const float* __restrict__ conv_w,  // [C, KW]
    const float* __restrict__ conv_b)  // [1]
{
    cudaTriggerProgrammaticLaunchCompletion();   // let K2 start prefetching w2

    const int tid  = threadIdx.x;
    const int lane = tid & 31;
    const int warp = tid >> 5;
    const int b    = blockIdx.x;

    if (b < C) {
        // ---------------- FC block: no barrier anywhere -------------------
        const bool tail = (lane < W - 64);               // 13-element tail
        const float* xr = x + b * W;
        const float x0 = xr[lane];
        const float x1 = xr[lane + 32];
        const float x2 = tail ? xr[lane + 64] : 0.f;

        const int d0 = warp * 2;
        const float* r0 = fc_w + (size_t)(b * FC + d0) * W;
        const float* r1 = r0 + W;
        const float f00 = r0[lane], f01 = r0[lane + 32], f02 = tail ? r0[lane + 64] : 0.f;
        const float f10 = r1[lane], f11 = r1[lane + 32], f12 = tail ? r1[lane + 64] : 0.f;
        const float bia0 = fc_b[b * FC + d0];
        const float bia1 = fc_b[b * FC + d0 + 1];

        float s0 = f00 * x0 + f01 * x1 + f02 * x2;
        float s1 = f10 * x0 + f11 * x1 + f12 * x2;
        s0 = warp_reduce(s0);
        s1 = warp_reduce(s1);
        if (lane == 0) {
            g_concat[b * FC + d0]     = s0 + bia0;
            g_concat[b * FC + d0 + 1] = s1 + bia1;
        }
    } else {
        // ------------------------- conv block -----------------------------
        __shared__ float xs[C * W];                      // 44.4 KB
        __shared__ float convv[CONV_OUT];

        for (int i = tid; i < C * W; i += K1NT) xs[i] = x[i];
        if (tid < CONV_OUT) convv[tid] = 0.f;
        __syncthreads();

        // warp w handles channels w, w+32, w+64, w+96, w+128
        float s0 = 0.f, s1 = 0.f, s2 = 0.f;              // outputs lane,+32,+64
        for (int ch = warp; ch < C; ch += 32) {
            const float* xrow = xs + ch * W;
#pragma unroll
            for (int k = 0; k < KW; k++) {
                const float cv = __ldg(&conv_w[ch * KW + k]);   // warp-uniform
                s0 += xrow[lane + k]      * cv;
                s1 += xrow[lane + 32 + k] * cv;
                if (lane < CONV_OUT - 64)                // 4 tail outputs
                    s2 += xrow[lane + 64 + k] * cv;
            }
        }
        atomicAdd(&convv[lane],      s0);
        atomicAdd(&convv[lane + 32], s1);
        if (lane < CONV_OUT - 64) atomicAdd(&convv[lane + 64], s2);
        __syncthreads();

        if (tid < CONV_OUT)
            g_concat[C * FC + tid] = convv[tid] + conv_b[0];
    }
    // implicit completion -> K2's cudaGridDependencySynchronize() releases
}

// ---------------------------------------------------------------------------
// K2 (PDL secondary): block j computes h[j] = relu(w2[j]·concat + b2[j]).
//   Prefetches the full 37 KB w2 row into registers BEFORE the dependency
//   sync -> the 4.75 MB w2 stream overlaps K1 entirely.
//   Final scalar layer via single-accumulator + counter; last block emits
//   sigmoid output and resets scratch for the next graph replay.
// ---------------------------------------------------------------------------
__global__ __launch_bounds__(K2NT) void k2_head(
    const float* __restrict__ w2,   // [H2, CONCAT]
    const float* __restrict__ b2,   // [H2]
    const float* __restrict__ w3,   // [1, H2]
    const float* __restrict__ b3,   // [1]
    float* __restrict__ out)        // [1]
{
    const int j    = blockIdx.x;
    const int tid  = threadIdx.x;
    const int lane = tid & 31;
    const int warp = tid >> 5;

    __shared__ float red[K2NT / 32];

    // ---- prefetch w2 row j into registers (overlaps K1) ----
    const float4* row = reinterpret_cast<const float4*>(w2 + (size_t)j * CONCAT);
    float4 wreg[5];
#pragma unroll
    for (int k = 0; k < 4; k++) wreg[k] = row[tid + k * K2NT];   // 0..2047
    const bool has5 = (tid < NV4 - 4 * K2NT);                    // tid < 273
    wreg[4] = has5 ? row[4 * K2NT + tid] : make_float4(0.f, 0.f, 0.f, 0.f);
    const float bias = b2[j];
    const float wout = w3[j];

    // ---- wait for K1 (all g_concat writes visible after this) ----
    cudaGridDependencySynchronize();

    // ---- dot with g_concat straight from L2 (just written) ----
    const float4* cc = reinterpret_cast<const float4*>(g_concat);
    float s = 0.f;
#pragma unroll
    for (int k = 0; k < 4; k++) s += dot4(wreg[k], cc[tid + k * K2NT]);
    if (has5) s += dot4(wreg[4], cc[4 * K2NT + tid]);

    // ---- block reduce ----
    s = warp_reduce(s);
    if (lane == 0) red[warp] = s;
    __syncthreads();
    if (warp == 0) {
        float v = (lane < K2NT / 32) ? red[lane] : 0.f;
        v = warp_reduce(v);
        if (lane == 0) {
            const float h = fmaxf(v + bias, 0.f);
            atomicAdd(&g_acc, h * wout);
            __threadfence();
            const unsigned n = atomicAdd(&g_cnt, 1u);
            if (n == H2 - 1) {
                const float total = atomicExch(&g_acc, 0.f);
                g_cnt = 0u;                       // reset for next replay
                const float o2 = fmaxf(total + b3[0], 0.f);
                out[0] = 1.f / (1.f + __expf(-o2));
            }
        }
    }
}

// ---------------------------------------------------------------------------
extern "C" void kernel_launch(void* const* d_in, const int* in_sizes, int n_in,
                              void* d_out, int out_size) {
    const float* x      = (const float*)d_in[0];
    const float* fc_w   = (const float*)d_in[1];
    const float* fc_b   = (const float*)d_in[2];
    const float* conv_w = (const float*)d_in[3];
    const float* conv_b = (const float*)d_in[4];
    const float* w2     = (const float*)d_in[5];
    const float* b2     = (const float*)d_in[6];
    const float* w3     = (const float*)d_in[7];
    const float* b3     = (const float*)d_in[8];
    float* out          = (float*)d_out;

    // primary
    k1_concat<<<K1GRID, K1NT>>>(x, fc_w, fc_b, conv_w, conv_b);

    // secondary with programmatic dependent launch (overlaps K1)
    cudaLaunchConfig_t cfg = {};
    cfg.gridDim  = dim3(K2GRID, 1, 1);
    cfg.blockDim = dim3(K2NT, 1, 1);
    cfg.dynamicSmemBytes = 0;
    cfg.stream = 0;                       // legacy default stream (captured)
    cudaLaunchAttribute attr[1];
    attr[0].id = cudaLaunchAttributeProgrammaticStreamSerialization;
    attr[0].val.programmaticStreamSerializationAllowed = 1;
    cfg.attrs = attr;
    cfg.numAttrs = 1;
    cudaLaunchKernelEx(&cfg, k2_head, w2, b2, w3, b3, out);
}

// round 11
// speedup vs baseline: 1.3732x; 1.3732x over previous
#include <cuda_runtime.h>
#include <math.h>
#include <stdint.h>

#define C        144
#define W        77
#define KW       10
#define FC       64
#define CONV_OUT 68                    // W - KW + 1
#define CONCAT   (C*FC + CONV_OUT)     // 9284
#define H2       128
#define GRID     C                     // one block per channel
#define NT       1024
#define PAD      64                    // 256 B accumulator stride (L2 slice spread)

// ---- dynamic smem layout (bytes) ----
#define SM_FCW   0                     // 64*77*4      = 19712 (16B mult)
#define SM_W2    19712                 // 128*64*4     = 32768
#define SM_FCB   52480                 // 64*4         = 256
#define SM_MBAR  52736                 // 8
#define SM_XS    52744                 // 77*4         = 308
#define SM_CW    53052                 // 10*4         = 40
#define SM_VALS  53104                 // 64*4 (16B aligned)
#define SM_CONVV 53360                 // 68*4
#define SM_SMH   53632                 // 128*4
#define SM_LAST  54144                 // 4
#define SMEM_TOTAL 54400

#define FCW_BYTES (FC * W * 4)         // 19712
#define TX_TOTAL  (FCW_BYTES + 32768 + 256)   // 52736

// Scratch (no device allocation allowed); zeroed at load, reset by last block.
__device__ __align__(256) float g_hp[H2 * PAD];
__device__ __align__(256) float g_convp[CONV_OUT * PAD];
__device__ unsigned int g_cnt = 0u;

__device__ __forceinline__ float warp_reduce(float v) {
#pragma unroll
    for (int o = 16; o > 0; o >>= 1) v += __shfl_down_sync(0xffffffffu, v, o);
    return v;
}

__device__ __forceinline__ float dot4(float4 a, float4 b) {
    return a.x * b.x + a.y * b.y + a.z * b.z + a.w * b.w;
}

__device__ __forceinline__ uint32_t smem_u32(const void* p) {
    uint32_t a;
    asm("{ .reg .u64 t; cvta.to.shared.u64 t, %1; cvt.u32.u64 %0, t; }"
        : "=r"(a) : "l"(p));
    return a;
}

__device__ __forceinline__ void bulk_copy(uint32_t dst, const void* src,
                                          uint32_t bytes, uint32_t mbar) {
    asm volatile(
        "cp.async.bulk.shared::cta.global.mbarrier::complete_tx::bytes "
        "[%0], [%1], %2, [%3];"
        :: "r"(dst), "l"(src), "r"(bytes), "r"(mbar) : "memory");
}

// ---------------------------------------------------------------------------
// Bulk-copy fused kernel, one 1024-thread block per channel.
//   All heavy operands (fc_w slice, fc_b slice, w2 column slice) arrive in
//   SMEM via cp.async.bulk (TMA engine) -> no per-thread LDG in-flight cap.
//   Compute runs from SMEM; padded global atomics accumulate h; last block
//   (counter) does conv matvec + final layers + scratch reset.
// ---------------------------------------------------------------------------
__global__ __launch_bounds__(NT, 1) void fused_kernel(
    const float* __restrict__ x,       // [C, W]
    const float* __restrict__ fc_w,    // [C, FC, W]
    const float* __restrict__ fc_b,    // [C, FC]
    const float* __restrict__ conv_w,  // [C, KW]
    const float* __restrict__ conv_b,  // [1]
    const float* __restrict__ w2,      // [H2, CONCAT]
    const float* __restrict__ b2,      // [H2]
    const float* __restrict__ w3,      // [1, H2]
    const float* __restrict__ b3,      // [1]
    float* __restrict__ out)           // [1]
{
    extern __shared__ __align__(128) char smem[];
    float* fcw_s  = (float*)(smem + SM_FCW);
    float* w2_s   = (float*)(smem + SM_W2);
    float* fcb_s  = (float*)(smem + SM_FCB);
    float* xs     = (float*)(smem + SM_XS);
    float* cw     = (float*)(smem + SM_CW);
    float* vals   = (float*)(smem + SM_VALS);
    float* convv  = (float*)(smem + SM_CONVV);
    float* sm_h   = (float*)(smem + SM_SMH);
    unsigned int* s_last = (unsigned int*)(smem + SM_LAST);

    const int tid  = threadIdx.x;
    const int lane = tid & 31;
    const int warp = tid >> 5;
    const int c    = blockIdx.x;

    const uint32_t mbar = smem_u32(smem + SM_MBAR);

    // ---- init mbarrier: 130 arrivers (128 w2 rows + fc_w + fc_b) ----
    if (tid == 0)
        asm volatile("mbarrier.init.shared.b64 [%0], %1;"
                     :: "r"(mbar), "r"(130u) : "memory");
    __syncthreads();

    // ---- scalar preloads (tiny) ----
    if (tid < W)            xs[tid]     = x[c * W + tid];
    else if (tid < W + KW)  cw[tid - W] = conv_w[c * KW + (tid - W)];

    // ---- issue bulk copies (each issuer: arrive.expect_tx then copy) ----
    if (tid >= 128 && tid < 258) {
        if (tid < 256) {
            const int j = tid - 128;                     // w2 row j, 256 B
            asm volatile("mbarrier.arrive.expect_tx.shared.b64 _, [%0], %1;"
                         :: "r"(mbar), "r"(256u) : "memory");
            bulk_copy(smem_u32(w2_s + j * FC),
                      w2 + (size_t)j * CONCAT + c * FC, 256u, mbar);
        } else if (tid == 256) {                         // fc_w slice, 19712 B
            asm volatile("mbarrier.arrive.expect_tx.shared.b64 _, [%0], %1;"
                         :: "r"(mbar), "r"((uint32_t)FCW_BYTES) : "memory");
            bulk_copy(smem_u32(fcw_s),
                      fc_w + (size_t)c * FC * W, (uint32_t)FCW_BYTES, mbar);
        } else {                                         // fc_b slice, 256 B
            asm volatile("mbarrier.arrive.expect_tx.shared.b64 _, [%0], %1;"
                         :: "r"(mbar), "r"(256u) : "memory");
            bulk_copy(smem_u32(fcb_s), fc_b + c * FC, 256u, mbar);
        }
    }

    // ---- wait for all bulk copies (phase 0) ----
    {
        uint32_t done;
        asm volatile(
            "{\n\t.reg .pred p;\n\t"
            "mbarrier.try_wait.parity.acquire.cta.shared::cta.b64 p, [%1], 0;\n\t"
            "selp.b32 %0, 1, 0, p;\n\t}"
            : "=r"(done) : "r"(mbar) : "memory");
        while (!done) {
            asm volatile(
                "{\n\t.reg .pred p;\n\t"
                "mbarrier.try_wait.parity.acquire.cta.shared::cta.b64 p, [%1], 0, 0x989680;\n\t"
                "selp.b32 %0, 1, 0, p;\n\t}"
                : "=r"(done) : "r"(mbar) : "memory");
        }
    }
    __syncthreads();                   // also orders xs/cw scalar stores

    // ---- FC from smem: 32 warps x 2 outputs ----
    {
        const bool tail = (lane < W - 64);
        const float x0 = xs[lane];
        const float x1 = xs[lane + 32];
        const float x2 = tail ? xs[lane + 64] : 0.f;
        const int d0 = warp * 2;
        const float* r0 = fcw_s + d0 * W;
        const float* r1 = r0 + W;
        float s0 = r0[lane] * x0 + r0[lane + 32] * x1 + (tail ? r0[lane + 64] * x2 : 0.f);
        float s1 = r1[lane] * x0 + r1[lane + 32] * x1 + (tail ? r1[lane + 64] * x2 : 0.f);
        s0 = warp_reduce(s0);
        s1 = warp_reduce(s1);
        if (lane == 0) {
            vals[d0]     = s0 + fcb_s[d0];
            vals[d0 + 1] = s1 + fcb_s[d0 + 1];
        }
    }

    // ---- conv contribution (padded RED) ----
    if (tid < CONV_OUT) {
        float s = 0.f;
#pragma unroll
        for (int k = 0; k < KW; k++) s += xs[tid + k] * cw[k];
        atomicAdd(&g_convp[tid * PAD], s);
    }
    __syncthreads();                   // vals visible

    // ---- g_hp[j*PAD] += w2_slice[j,:] . vals (from smem) ----
    const int j = tid >> 3;            // 0..127
    const int p = tid & 7;             // 0..7
    {
        const float4* wr = reinterpret_cast<const float4*>(w2_s + j * FC);
        const float4* v4 = reinterpret_cast<const float4*>(vals);
        float s = dot4(wr[p], v4[p]) + dot4(wr[p + 8], v4[p + 8]);
#pragma unroll
        for (int o = 4; o > 0; o >>= 1)
            s += __shfl_down_sync(0xffffffffu, s, o, 8);
        if (p == 0) {
            atomicAdd(&g_hp[j * PAD], s);
            __threadfence();           // release my RED before my arrive
        }
    }

    // ---- last-block election (no spinning; non-last blocks exit) ----
    __syncthreads();
    if (tid == 0)
        *s_last = (atomicAdd(&g_cnt, 1u) == GRID - 1) ? 1u : 0u;
    __syncthreads();
    if (*s_last == 0u) return;

    // =================== finalization (last block only) ==================
    __threadfence();                   // acquire all g_hp / g_convp updates

    if (tid < CONV_OUT) {
        convv[tid]          = g_convp[tid * PAD] + conv_b[0];
        g_convp[tid * PAD]  = 0.f;     // reset for next replay
    }
    __syncthreads();

    // conv matvec: h[j] += w2[j, 9216:9284] . convv ; then relu & w3 weight
    {
        const float4* rw = reinterpret_cast<const float4*>(
            w2 + (size_t)j * CONCAT + C * FC);           // 16B-aligned
        const float4* cv = reinterpret_cast<const float4*>(convv);
        float s = dot4(rw[p], cv[p]) + dot4(rw[p + 8], cv[p + 8]);
        if (p == 0) s += dot4(rw[16], cv[16]);           // 17th float4
#pragma unroll
        for (int o = 4; o > 0; o >>= 1)
            s += __shfl_down_sync(0xffffffffu, s, o, 8);
        if (p == 0) {
            const float pre = g_hp[j * PAD] + s + b2[j];
            sm_h[j] = fmaxf(pre, 0.f) * w3[j];
            g_hp[j * PAD] = 0.f;       // reset for next replay
        }
    }
    __syncthreads();

    if (warp == 0) {
        float v = sm_h[lane] + sm_h[lane + 32]
                + sm_h[lane + 64] + sm_h[lane + 96];
        v = warp_reduce(v);
        if (lane == 0) {
            const float o2 = fmaxf(v + b3[0], 0.f);
            out[0] = 1.f / (1.f + __expf(-o2));
            g_cnt  = 0u;               // reset for next replay
        }
    }
}

// ---------------------------------------------------------------------------
extern "C" void kernel_launch(void* const* d_in, const int* in_sizes, int n_in,
                              void* d_out, int out_size) {
    const float* x      = (const float*)d_in[0];
    const float* fc_w   = (const float*)d_in[1];
    const float* fc_b   = (const float*)d_in[2];
    const float* conv_w = (const float*)d_in[3];
    const float* conv_b = (const float*)d_in[4];
    const float* w2     = (const float*)d_in[5];
    const float* b2     = (const float*)d_in[6];
    const float* w3     = (const float*)d_in[7];
    const float* b3     = (const float*)d_in[8];

    cudaFuncSetAttribute(fused_kernel,
                         cudaFuncAttributeMaxDynamicSharedMemorySize,
                         SMEM_TOTAL);
    fused_kernel<<<GRID, NT, SMEM_TOTAL>>>(x, fc_w, fc_b, conv_w, conv_b,
                                           w2, b2, w3, b3, (float*)d_out);
}